// round 6
// baseline (speedup 1.0000x reference)
#include <cuda_runtime.h>
#include <math.h>
#include <stdint.h>

#define NH 8
#define CDIM 512
#define HW 256
#define CH 64
#define BATCH 4
#define TCACHE 63
#define SK 72                 // smem row stride (words)
#define LOG2E 1.4426950408889634f

__device__ float g_wqkv_n[3 * CDIM * CDIM];
__device__ float g_wproj_n[CDIM * CDIM];
__device__ float2 g_rope[64 * 32];          // {cos,sin}[t][j]
__device__ float g_q[BATCH * NH * HW * CH];
__device__ float g_k[BATCH * NH * HW * CH];
__device__ float g_v[BATCH * NH * HW * CH];
__device__ float g_o[BATCH * CDIM * HW];    // [b][ch*NH+head][s]
// split-KV partials: [(((b*8+h)*2+qp)*2+kvh)] x [ch 64][row 128]
__device__ float g_po[BATCH * NH * 2 * 2 * 64 * 128];
__device__ float g_pm[BATCH * NH * 2 * 2 * 128];
__device__ float g_pl[BATCH * NH * 2 * 2 * 128];

__device__ __forceinline__ unsigned f2tf(float x) {
    unsigned r;
    asm("cvt.rna.tf32.f32 %0, %1;" : "=r"(r) : "f"(x));
    return r;
}
__device__ __forceinline__ float ex2(float x) {
    float y;
    asm("ex2.approx.f32 %0, %1;" : "=f"(y) : "f"(x));
    return y;
}
__device__ __forceinline__ void mma8(float c[4], const unsigned a[4], unsigned b0, unsigned b1) {
    asm volatile(
        "mma.sync.aligned.m16n8k8.row.col.f32.tf32.tf32.f32 "
        "{%0,%1,%2,%3}, {%4,%5,%6,%7}, {%8,%9}, {%0,%1,%2,%3};\n"
        : "+f"(c[0]), "+f"(c[1]), "+f"(c[2]), "+f"(c[3])
        : "r"(a[0]), "r"(a[1]), "r"(a[2]), "r"(a[3]), "r"(b0), "r"(b1));
}
// logical r (0..7) in an 8-group -> physical slot so frag pair (r, r+4) is adjacent
__device__ __forceinline__ int pc8(int r) { return ((r & 3) << 1) | (r >> 2); }

__device__ __forceinline__ void cpa16(uint32_t dst, const void* src) {
    asm volatile("cp.async.cg.shared.global [%0], [%1], 16;" :: "r"(dst), "l"(src));
}
#define CP_COMMIT() asm volatile("cp.async.commit_group;")
#define CP_WAIT1()  asm volatile("cp.async.wait_group 1;")

// ---------------- K1a: mp_weight row normalization ----------------
__global__ void norm_kernel(const float* __restrict__ wq, const float* __restrict__ wp) {
    int r = blockIdx.x;
    const float* src;
    float* dst;
    if (r < 3 * CDIM) { src = wq + (size_t)r * CDIM; dst = g_wqkv_n + (size_t)r * CDIM; }
    else { int rr = r - 3 * CDIM; src = wp + (size_t)rr * CDIM; dst = g_wproj_n + (size_t)rr * CDIM; }

    float4 v = reinterpret_cast<const float4*>(src)[threadIdx.x];
    float ss = v.x * v.x + v.y * v.y + v.z * v.z + v.w * v.w;
    for (int o = 16; o; o >>= 1) ss += __shfl_xor_sync(0xffffffffu, ss, o);
    __shared__ float wsum[4];
    if ((threadIdx.x & 31) == 0) wsum[threadIdx.x >> 5] = ss;
    __syncthreads();
    float nrm = sqrtf(wsum[0] + wsum[1] + wsum[2] + wsum[3]);
    float s512 = sqrtf((float)CDIM);
    float scale = 1.0f / ((1e-4f + nrm / s512) * s512);
    float4 o4;
    o4.x = v.x * scale; o4.y = v.y * scale; o4.z = v.z * scale; o4.w = v.w * scale;
    reinterpret_cast<float4*>(dst)[threadIdx.x] = o4;
}

// ---------------- K1b: rope table ----------------
__global__ void rope_table_kernel() {
    int idx = blockIdx.x * blockDim.x + threadIdx.x;
    if (idx < 64 * 32) {
        int t = idx >> 5, j = idx & 31;
        float inv = powf(10000.0f, -(2.0f * (float)j) / 64.0f);
        float a = (float)t * inv;
        g_rope[idx] = make_float2(cosf(a), sinf(a));
    }
}

// ---------------- K2: QKV GEMM (fp32) -> q/k/v [b][head][s][ch] ----------------
__global__ __launch_bounds__(256) void qkv_gemm_kernel(const float* __restrict__ x) {
    __shared__ float As[16][68];
    __shared__ float Bs[16][68];
    int bb = blockIdx.z;
    int m0 = blockIdx.y * 64;
    int n0 = blockIdx.x * 64;
    int tid = threadIdx.x;
    int ty = tid >> 4, tx = tid & 15;
    float acc[4][4] = {};

    for (int k0 = 0; k0 < CDIM; k0 += 16) {
        {
            int lin = tid * 4;
            int mi = lin >> 4, ki = lin & 15;
            float4 a = *reinterpret_cast<const float4*>(&g_wqkv_n[(size_t)(m0 + mi) * CDIM + k0 + ki]);
            As[ki + 0][mi] = a.x; As[ki + 1][mi] = a.y; As[ki + 2][mi] = a.z; As[ki + 3][mi] = a.w;
        }
        {
            int lin = tid * 4;
            int ki = lin >> 6, ni = lin & 63;
            float4 b = *reinterpret_cast<const float4*>(&x[((size_t)bb * CDIM + k0 + ki) * HW + n0 + ni]);
            *reinterpret_cast<float4*>(&Bs[ki][ni]) = b;
        }
        __syncthreads();
#pragma unroll
        for (int kk = 0; kk < 16; kk++) {
            float4 a = *reinterpret_cast<const float4*>(&As[kk][ty * 4]);
            float4 b = *reinterpret_cast<const float4*>(&Bs[kk][tx * 4]);
            float av[4] = {a.x, a.y, a.z, a.w};
            float bv[4] = {b.x, b.y, b.z, b.w};
#pragma unroll
            for (int i = 0; i < 4; i++)
#pragma unroll
                for (int j = 0; j < 4; j++) acc[i][j] += av[i] * bv[j];
        }
        __syncthreads();
    }

    int which = m0 >> 9;
    int head = (m0 >> 6) & 7;
    float* dst = (which == 0) ? g_q : ((which == 1) ? g_k : g_v);
#pragma unroll
    for (int i = 0; i < 4; i++) {
        int ch = ty * 4 + i;
#pragma unroll
        for (int j = 0; j < 4; j++) {
            int s = n0 + tx * 4 + j;
            dst[(((size_t)bb * NH + head) * HW + s) * CH + ch] = acc[i][j];
        }
    }
}

// ---------------- K3: flash attention v3 (256 thr / 8 warps) ----------------
// grid (4, 8, 4): x -> qp = x>>1 (128-q-row block), kvh = x&1 (128-kv-iter half)
// Each warp owns one m16 q-strip (rows 16w..16w+15 of the 128).
__global__ __launch_bounds__(256, 1) void attn_kernel(const float* __restrict__ ck,
                                                      const float* __restrict__ cv) {
    extern __shared__ float smf[];
    float* Kr = smf;                  // 2 stages x 64 x SK  (raw -> roped+permuted in place)
    float* Vr = smf + 2 * 64 * SK;    // 2 stages x 64 x SK  (raw)
    float* Vt = smf + 4 * 64 * SK;    // 64 ch x SK          (transposed, key-permuted)
    float* Ps = smf + 5 * 64 * SK;    // 128 q x SK          (Q staging, then P)
    float2* Tab = reinterpret_cast<float2*>(smf + 7 * 64 * SK);  // 64 x 32

    int qp = blockIdx.x >> 1, kvh = blockIdx.x & 1;
    int head = blockIdx.y, bb = blockIdx.z;
    int bhi = bb * NH + head;
    int tid = threadIdx.x;
    int w = tid >> 5, l = tid & 31;
    int la = l >> 2, lb = l & 3;

    uint32_t kr_u = (uint32_t)__cvta_generic_to_shared(Kr);
    uint32_t vr_u = (uint32_t)__cvta_generic_to_shared(Vr);

    // issue cp.async for iteration i into stage i&1 (256 threads: quarter-row each)
    auto issue_tile = [&](int i) {
        int ktg = kvh * 128 + i;
        int t = ktg >> 2, st = ktg & 3;
        const float *kp, *vp;
        if (t < TCACHE) {
            size_t base = (((size_t)bhi * TCACHE + t) * HW + st * 64);
            kp = ck + base * CH; vp = cv + base * CH;
        } else {
            size_t base = ((size_t)bhi * HW + st * 64);
            kp = g_k + base * CH; vp = g_v + base * CH;
        }
        int s = i & 1;
        int krow = tid >> 2, qtr = tid & 3;
        uint32_t kd = kr_u + (uint32_t)(s * 64 * SK + krow * SK + qtr * 16) * 4u;
        uint32_t vd = vr_u + (uint32_t)(s * 64 * SK + krow * SK + qtr * 16) * 4u;
        const float* ks = kp + krow * CH + qtr * 16;
        const float* vs = vp + krow * CH + qtr * 16;
#pragma unroll
        for (int c = 0; c < 4; c++) {
            cpa16(kd + c * 16, ks + c * 4);
            cpa16(vd + c * 16, vs + c * 4);
        }
    };

    issue_tile(0); CP_COMMIT();
    issue_tile(1); CP_COMMIT();

    // rope table -> smem
#pragma unroll
    for (int i = 0; i < 8; i++) Tab[tid + i * 256] = g_rope[tid + i * 256];
    __syncthreads();

    // stage Q: rope(pos 63), * log2e/8, tf32, permuted (half a row per thread)
    {
        int r = tid >> 1, half = tid & 1;
        const float* qpv = g_q + (((size_t)bhi) * HW + qp * 128 + r) * CH + half * 32;
        const float2* tq = Tab + 63 * 32 + half * 16;
        const float sc = 0.125f * LOG2E;
        unsigned* pr = reinterpret_cast<unsigned*>(Ps + r * SK) + half * 32;
#pragma unroll
        for (int g = 0; g < 4; g++) {
            float4 x0 = *reinterpret_cast<const float4*>(qpv + 8 * g);
            float4 x1 = *reinterpret_cast<const float4*>(qpv + 8 * g + 4);
            float2 t0 = tq[4 * g], t1 = tq[4 * g + 1], t2 = tq[4 * g + 2], t3 = tq[4 * g + 3];
            float l0 = (x0.x * t0.x - x0.y * t0.y) * sc;
            float l1 = (x0.x * t0.y + x0.y * t0.x) * sc;
            float l2 = (x0.z * t1.x - x0.w * t1.y) * sc;
            float l3 = (x0.z * t1.y + x0.w * t1.x) * sc;
            float l4 = (x1.x * t2.x - x1.y * t2.y) * sc;
            float l5 = (x1.x * t2.y + x1.y * t2.x) * sc;
            float l6 = (x1.z * t3.x - x1.w * t3.y) * sc;
            float l7 = (x1.z * t3.y + x1.w * t3.x) * sc;
            pr[8 * g + 0] = f2tf(l0); pr[8 * g + 1] = f2tf(l4);
            pr[8 * g + 2] = f2tf(l1); pr[8 * g + 3] = f2tf(l5);
            pr[8 * g + 4] = f2tf(l2); pr[8 * g + 5] = f2tf(l6);
            pr[8 * g + 6] = f2tf(l3); pr[8 * g + 7] = f2tf(l7);
        }
    }
    __syncthreads();

    // Q fragments: warp w owns rows 16w..16w+15
    unsigned qa[8][4];
    {
        int r0 = 16 * w + la;
#pragma unroll
        for (int kk = 0; kk < 8; kk++) {
            uint2 p0 = *reinterpret_cast<const uint2*>(&Ps[r0 * SK + kk * 8 + 2 * lb]);
            uint2 p1 = *reinterpret_cast<const uint2*>(&Ps[(r0 + 8) * SK + kk * 8 + 2 * lb]);
            qa[kk][0] = p0.x; qa[kk][1] = p1.x; qa[kk][2] = p0.y; qa[kk][3] = p1.y;
        }
    }
    __syncthreads();

    float oacc[8][4] = {};
    float rm0 = -1e30f, rm1 = -1e30f, ls0 = 0.f, ls1 = 0.f;
    const int P0 = pc8(2 * lb), P1 = pc8(2 * lb + 1);
    const int prow = 16 * w + la;

    for (int i = 0; i < 128; i++) {
        int s = i & 1;
        CP_WAIT1();
        __syncthreads();

        // ---- convert: K rope+permute in place; V transpose+permute into Vt ----
        {
            int t = (kvh * 128 + i) >> 2;
            int krow = tid >> 2, qtr = tid & 3;
            float* kb = Kr + s * 64 * SK + krow * SK;
            const float2* tt_ = Tab + t * 32 + qtr * 8;
#pragma unroll
            for (int g2 = 0; g2 < 2; g2++) {
                int ch0 = qtr * 16 + g2 * 8;
                float4 a = *reinterpret_cast<const float4*>(kb + ch0);
                float4 b = *reinterpret_cast<const float4*>(kb + ch0 + 4);
                float2 t0 = tt_[4 * g2], t1 = tt_[4 * g2 + 1], t2 = tt_[4 * g2 + 2], t3 = tt_[4 * g2 + 3];
                float l0 = a.x * t0.x - a.y * t0.y;
                float l1 = a.x * t0.y + a.y * t0.x;
                float l2 = a.z * t1.x - a.w * t1.y;
                float l3 = a.z * t1.y + a.w * t1.x;
                float l4 = b.x * t2.x - b.y * t2.y;
                float l5 = b.x * t2.y + b.y * t2.x;
                float l6 = b.z * t3.x - b.w * t3.y;
                float l7 = b.z * t3.y + b.w * t3.x;
                unsigned* o = reinterpret_cast<unsigned*>(kb + ch0);
                o[0] = f2tf(l0); o[1] = f2tf(l4); o[2] = f2tf(l1); o[3] = f2tf(l5);
                o[4] = f2tf(l2); o[5] = f2tf(l6); o[6] = f2tf(l3); o[7] = f2tf(l7);
            }
            float* vb = Vr + s * 64 * SK + krow * SK;
            int pk = (krow & ~7) | pc8(krow & 7);
            unsigned* vt = reinterpret_cast<unsigned*>(Vt);
#pragma unroll
            for (int c = 0; c < 4; c++) {
                int ch0 = qtr * 16 + c * 4;
                float4 v = *reinterpret_cast<const float4*>(vb + ch0);
                vt[(ch0 + 0) * SK + pk] = f2tf(v.x);
                vt[(ch0 + 1) * SK + pk] = f2tf(v.y);
                vt[(ch0 + 2) * SK + pk] = f2tf(v.z);
                vt[(ch0 + 3) * SK + pk] = f2tf(v.w);
            }
        }
        __syncthreads();

        // ---- S = Q K^T (16 x 64 per warp) ----
        const float* Kb = Kr + s * 64 * SK;
        float sc[8][4];
#pragma unroll
        for (int nn = 0; nn < 8; nn++) {
            sc[nn][0] = sc[nn][1] = sc[nn][2] = sc[nn][3] = 0.f;
            const float* kr = Kb + (nn * 8 + la) * SK;
#pragma unroll
            for (int kk = 0; kk < 8; kk++) {
                uint2 b = *reinterpret_cast<const uint2*>(kr + kk * 8 + 2 * lb);
                mma8(sc[nn], qa[kk], b.x, b.y);
            }
        }

        // ---- online softmax ----
        float mx0 = -1e30f, mx1 = -1e30f;
#pragma unroll
        for (int nn = 0; nn < 8; nn++) {
            mx0 = fmaxf(mx0, fmaxf(sc[nn][0], sc[nn][1]));
            mx1 = fmaxf(mx1, fmaxf(sc[nn][2], sc[nn][3]));
        }
        mx0 = fmaxf(mx0, __shfl_xor_sync(0xffffffffu, mx0, 1));
        mx0 = fmaxf(mx0, __shfl_xor_sync(0xffffffffu, mx0, 2));
        mx1 = fmaxf(mx1, __shfl_xor_sync(0xffffffffu, mx1, 1));
        mx1 = fmaxf(mx1, __shfl_xor_sync(0xffffffffu, mx1, 2));
        float mn0 = fmaxf(rm0, mx0), mn1 = fmaxf(rm1, mx1);
        float al0 = ex2(rm0 - mn0), al1 = ex2(rm1 - mn1);
        float s0 = 0.f, s1 = 0.f;
        float* pr0 = Ps + prow * SK;
        float* pr1 = Ps + (prow + 8) * SK;
#pragma unroll
        for (int nn = 0; nn < 8; nn++) {
            float p0 = ex2(sc[nn][0] - mn0);
            float p1 = ex2(sc[nn][1] - mn0);
            float p2 = ex2(sc[nn][2] - mn1);
            float p3 = ex2(sc[nn][3] - mn1);
            s0 += p0 + p1; s1 += p2 + p3;
            pr0[nn * 8 + P0] = p0;   // raw f32 bits; HW truncates to tf32
            pr0[nn * 8 + P1] = p1;
            pr1[nn * 8 + P0] = p2;
            pr1[nn * 8 + P1] = p3;
        }
        s0 += __shfl_xor_sync(0xffffffffu, s0, 1);
        s0 += __shfl_xor_sync(0xffffffffu, s0, 2);
        s1 += __shfl_xor_sync(0xffffffffu, s1, 1);
        s1 += __shfl_xor_sync(0xffffffffu, s1, 2);
        ls0 = ls0 * al0 + s0;
        ls1 = ls1 * al1 + s1;
        rm0 = mn0; rm1 = mn1;
#pragma unroll
        for (int nn = 0; nn < 8; nn++) {
            oacc[nn][0] *= al0; oacc[nn][1] *= al0;
            oacc[nn][2] *= al1; oacc[nn][3] *= al1;
        }
        __syncwarp();  // P rows are warp-private

        // ---- O += P V ----
#pragma unroll
        for (int kk = 0; kk < 8; kk++) {
            uint2 a0 = *reinterpret_cast<const uint2*>(&Ps[prow * SK + kk * 8 + 2 * lb]);
            uint2 a1 = *reinterpret_cast<const uint2*>(&Ps[(prow + 8) * SK + kk * 8 + 2 * lb]);
            unsigned A[4] = {a0.x, a1.x, a0.y, a1.y};
#pragma unroll
            for (int nn = 0; nn < 8; nn++) {
                uint2 b = *reinterpret_cast<const uint2*>(&Vt[(nn * 8 + la) * SK + kk * 8 + 2 * lb]);
                mma8(oacc[nn], A, b.x, b.y);
            }
        }

        __syncthreads();
        if (i + 2 < 128) issue_tile(i + 2);
        CP_COMMIT();
    }

    // ---- epilogue: write split-KV partials ----
    int pbase = ((bhi * 2 + qp) * 2 + kvh);
    float* po = g_po + (size_t)pbase * 8192;
    {
        int row = prow;
#pragma unroll
        for (int nn = 0; nn < 8; nn++) {
            int ch = nn * 8 + 2 * lb;
            po[(ch + 0) * 128 + row]     = oacc[nn][0];
            po[(ch + 1) * 128 + row]     = oacc[nn][1];
            po[(ch + 0) * 128 + row + 8] = oacc[nn][2];
            po[(ch + 1) * 128 + row + 8] = oacc[nn][3];
        }
        if (lb == 0) {
            g_pm[pbase * 128 + row]     = rm0;
            g_pl[pbase * 128 + row]     = ls0;
            g_pm[pbase * 128 + row + 8] = rm1;
            g_pl[pbase * 128 + row + 8] = ls1;
        }
    }
}

// ---------------- K3b: split-KV combine -> g_o ----------------
__global__ __launch_bounds__(256) void combine_kernel() {
    int qp = blockIdx.x, head = blockIdx.y, bb = blockIdx.z;
    int pb0 = (((bb * NH + head) * 2 + qp) * 2 + 0);
    int pb1 = pb0 + 1;
    int tid = threadIdx.x;
    __shared__ float w0s[128], w1s[128], il[128];
    if (tid < 128) {
        float m0 = g_pm[pb0 * 128 + tid], m1 = g_pm[pb1 * 128 + tid];
        float l0 = g_pl[pb0 * 128 + tid], l1 = g_pl[pb1 * 128 + tid];
        float M = fmaxf(m0, m1);
        float w0 = ex2(m0 - M), w1 = ex2(m1 - M);
        w0s[tid] = w0; w1s[tid] = w1;
        il[tid] = 1.0f / (w0 * l0 + w1 * l1);
    }
    __syncthreads();
    int ch = tid >> 2, sg = tid & 3;
    const float* p0 = g_po + (size_t)pb0 * 8192 + ch * 128;
    const float* p1 = g_po + (size_t)pb1 * 8192 + ch * 128;
    float* dst = g_o + ((size_t)bb * CDIM + (ch * NH + head)) * HW + qp * 128;
#pragma unroll 4
    for (int rr = 0; rr < 32; rr++) {
        int r = sg * 32 + rr;
        dst[r] = (w0s[r] * p0[r] + w1s[r] * p1[r]) * il[r];
    }
}

// ---------------- K4: proj GEMM + mp_sum ----------------
__global__ __launch_bounds__(256) void proj_kernel(const float* __restrict__ x,
                                                   float* __restrict__ out) {
    __shared__ float As[16][68];
    __shared__ float Bs[16][68];
    int bb = blockIdx.z;
    int m0 = blockIdx.y * 64;
    int n0 = blockIdx.x * 64;
    int tid = threadIdx.x;
    int ty = tid >> 4, tx = tid & 15;
    float acc[4][4] = {};

    for (int k0 = 0; k0 < CDIM; k0 += 16) {
        {
            int lin = tid * 4;
            int mi = lin >> 4, ki = lin & 15;
            float4 a = *reinterpret_cast<const float4*>(&g_wproj_n[(size_t)(m0 + mi) * CDIM + k0 + ki]);
            As[ki + 0][mi] = a.x; As[ki + 1][mi] = a.y; As[ki + 2][mi] = a.z; As[ki + 3][mi] = a.w;
        }
        {
            int lin = tid * 4;
            int ki = lin >> 6, ni = lin & 63;
            float4 b = *reinterpret_cast<const float4*>(&g_o[((size_t)bb * CDIM + k0 + ki) * HW + n0 + ni]);
            *reinterpret_cast<float4*>(&Bs[ki][ni]) = b;
        }
        __syncthreads();
#pragma unroll
        for (int kk = 0; kk < 16; kk++) {
            float4 a = *reinterpret_cast<const float4*>(&As[kk][ty * 4]);
            float4 b = *reinterpret_cast<const float4*>(&Bs[kk][tx * 4]);
            float av[4] = {a.x, a.y, a.z, a.w};
            float bv[4] = {b.x, b.y, b.z, b.w};
#pragma unroll
            for (int i = 0; i < 4; i++)
#pragma unroll
                for (int j = 0; j < 4; j++) acc[i][j] += av[i] * bv[j];
        }
        __syncthreads();
    }

    const float norm = 1.3130643286f;  // 1/sqrt(0.7^2+0.3^2)
#pragma unroll
    for (int i = 0; i < 4; i++) {
        int och = m0 + ty * 4 + i;
#pragma unroll
        for (int j = 0; j < 4; j++) {
            int s = n0 + tx * 4 + j;
            size_t idx = ((size_t)bb * CDIM + och) * HW + s;
            out[idx] = (0.7f * x[idx] + 0.3f * acc[i][j]) * norm;
        }
    }
}

extern "C" void kernel_launch(void* const* d_in, const int* in_sizes, int n_in,
                              void* d_out, int out_size) {
    const float* x     = (const float*)d_in[0];
    const float* ck    = (const float*)d_in[1];
    const float* cv    = (const float*)d_in[2];
    const float* wqkv  = (const float*)d_in[3];
    const float* wproj = (const float*)d_in[4];
    float* out = (float*)d_out;

    norm_kernel<<<4 * CDIM, 128>>>(wqkv, wproj);
    rope_table_kernel<<<8, 256>>>();
    qkv_gemm_kernel<<<dim3(4, 24, 4), 256>>>(x);

    int smem = (7 * 64 * SK + 64 * 32 * 2) * (int)sizeof(float);  // 145408 B
    cudaFuncSetAttribute(attn_kernel, cudaFuncAttributeMaxDynamicSharedMemorySize, smem);
    attn_kernel<<<dim3(4, NH, 4), 256, smem>>>(ck, cv);

    combine_kernel<<<dim3(2, NH, BATCH), 256>>>();
    proj_kernel<<<dim3(4, 8, 4), 256>>>(x, out);
}

// round 8
// speedup vs baseline: 1.5200x; 1.5200x over previous
#include <cuda_runtime.h>
#include <math.h>
#include <stdint.h>

#define NH 8
#define CDIM 512
#define HW 256
#define CH 64
#define BATCH 4
#define TCACHE 63
#define SK 72                 // smem row stride (words)
#define NKV 4                 // KV split factor
#define ITERS 64              // 256 subtiles / NKV
#define LOG2E 1.4426950408889634f

__device__ float g_wqkv_n[3 * CDIM * CDIM];
__device__ float g_wproj_n[CDIM * CDIM];
__device__ float2 g_rope[64 * 32];          // {cos,sin}[t][j]
__device__ float g_q[BATCH * NH * HW * CH];
__device__ float g_k[BATCH * NH * HW * CH];
__device__ float g_v[BATCH * NH * HW * CH];
__device__ float g_o[BATCH * CDIM * HW];    // [b][ch*NH+head][s]
// split-KV partials: [(((b*8+h)*2+qp)*NKV+kvq)] x [ch 64][row 128]
__device__ float g_po[BATCH * NH * 2 * NKV * 64 * 128];
__device__ float g_pm[BATCH * NH * 2 * NKV * 128];
__device__ float g_pl[BATCH * NH * 2 * NKV * 128];

__device__ __forceinline__ unsigned f2tf(float x) {
    unsigned r;
    asm("cvt.rna.tf32.f32 %0, %1;" : "=r"(r) : "f"(x));
    return r;
}
__device__ __forceinline__ float ex2(float x) {
    float y;
    asm("ex2.approx.f32 %0, %1;" : "=f"(y) : "f"(x));
    return y;
}
__device__ __forceinline__ void mma8(float c[4], const unsigned a[4], unsigned b0, unsigned b1) {
    asm volatile(
        "mma.sync.aligned.m16n8k8.row.col.f32.tf32.tf32.f32 "
        "{%0,%1,%2,%3}, {%4,%5,%6,%7}, {%8,%9}, {%0,%1,%2,%3};\n"
        : "+f"(c[0]), "+f"(c[1]), "+f"(c[2]), "+f"(c[3])
        : "r"(a[0]), "r"(a[1]), "r"(a[2]), "r"(a[3]), "r"(b0), "r"(b1));
}
// logical r (0..7) in an 8-group -> physical slot so frag pair (r, r+4) is adjacent
__device__ __forceinline__ int pc8(int r) { return ((r & 3) << 1) | (r >> 2); }

__device__ __forceinline__ void cpa16(uint32_t dst, const void* src) {
    asm volatile("cp.async.cg.shared.global [%0], [%1], 16;" :: "r"(dst), "l"(src));
}
#define CP_COMMIT() asm volatile("cp.async.commit_group;")
#define CP_WAIT1()  asm volatile("cp.async.wait_group 1;")

// ---------------- K1a: mp_weight row normalization ----------------
__global__ void norm_kernel(const float* __restrict__ wq, const float* __restrict__ wp) {
    int r = blockIdx.x;
    const float* src;
    float* dst;
    if (r < 3 * CDIM) { src = wq + (size_t)r * CDIM; dst = g_wqkv_n + (size_t)r * CDIM; }
    else { int rr = r - 3 * CDIM; src = wp + (size_t)rr * CDIM; dst = g_wproj_n + (size_t)rr * CDIM; }

    float4 v = reinterpret_cast<const float4*>(src)[threadIdx.x];
    float ss = v.x * v.x + v.y * v.y + v.z * v.z + v.w * v.w;
    for (int o = 16; o; o >>= 1) ss += __shfl_xor_sync(0xffffffffu, ss, o);
    __shared__ float wsum[4];
    if ((threadIdx.x & 31) == 0) wsum[threadIdx.x >> 5] = ss;
    __syncthreads();
    float nrm = sqrtf(wsum[0] + wsum[1] + wsum[2] + wsum[3]);
    float s512 = sqrtf((float)CDIM);
    float scale = 1.0f / ((1e-4f + nrm / s512) * s512);
    float4 o4;
    o4.x = v.x * scale; o4.y = v.y * scale; o4.z = v.z * scale; o4.w = v.w * scale;
    reinterpret_cast<float4*>(dst)[threadIdx.x] = o4;
}

// ---------------- K1b: rope table ----------------
__global__ void rope_table_kernel() {
    int idx = blockIdx.x * blockDim.x + threadIdx.x;
    if (idx < 64 * 32) {
        int t = idx >> 5, j = idx & 31;
        float inv = powf(10000.0f, -(2.0f * (float)j) / 64.0f);
        float a = (float)t * inv;
        g_rope[idx] = make_float2(cosf(a), sinf(a));
    }
}

// ---------------- K2: QKV GEMM (fp32) -> q/k/v [b][head][s][ch] ----------------
__global__ __launch_bounds__(256) void qkv_gemm_kernel(const float* __restrict__ x) {
    __shared__ float As[16][68];
    __shared__ float Bs[16][68];
    int bb = blockIdx.z;
    int m0 = blockIdx.y * 64;
    int n0 = blockIdx.x * 64;
    int tid = threadIdx.x;
    int ty = tid >> 4, tx = tid & 15;
    float acc[4][4] = {};

    for (int k0 = 0; k0 < CDIM; k0 += 16) {
        {
            int lin = tid * 4;
            int mi = lin >> 4, ki = lin & 15;
            float4 a = *reinterpret_cast<const float4*>(&g_wqkv_n[(size_t)(m0 + mi) * CDIM + k0 + ki]);
            As[ki + 0][mi] = a.x; As[ki + 1][mi] = a.y; As[ki + 2][mi] = a.z; As[ki + 3][mi] = a.w;
        }
        {
            int lin = tid * 4;
            int ki = lin >> 6, ni = lin & 63;
            float4 b = *reinterpret_cast<const float4*>(&x[((size_t)bb * CDIM + k0 + ki) * HW + n0 + ni]);
            *reinterpret_cast<float4*>(&Bs[ki][ni]) = b;
        }
        __syncthreads();
#pragma unroll
        for (int kk = 0; kk < 16; kk++) {
            float4 a = *reinterpret_cast<const float4*>(&As[kk][ty * 4]);
            float4 b = *reinterpret_cast<const float4*>(&Bs[kk][tx * 4]);
            float av[4] = {a.x, a.y, a.z, a.w};
            float bv[4] = {b.x, b.y, b.z, b.w};
#pragma unroll
            for (int i = 0; i < 4; i++)
#pragma unroll
                for (int j = 0; j < 4; j++) acc[i][j] += av[i] * bv[j];
        }
        __syncthreads();
    }

    int which = m0 >> 9;
    int head = (m0 >> 6) & 7;
    float* dst = (which == 0) ? g_q : ((which == 1) ? g_k : g_v);
#pragma unroll
    for (int i = 0; i < 4; i++) {
        int ch = ty * 4 + i;
#pragma unroll
        for (int j = 0; j < 4; j++) {
            int s = n0 + tx * 4 + j;
            dst[(((size_t)bb * NH + head) * HW + s) * CH + ch] = acc[i][j];
        }
    }
}

// ---------------- K3: flash attention v4 (128 thr, 2 q-tiles/warp, 4-way KV split) ----------------
// grid (8, 8, 4): x -> qp = x>>2 (128-q-row block), kvq = x&3 (64-iter KV quarter)
__global__ __launch_bounds__(128, 2) void attn_kernel(const float* __restrict__ ck,
                                                      const float* __restrict__ cv) {
    extern __shared__ float smf[];
    float* Kr = smf;                  // 2 stages x 64 x SK (raw -> roped+permuted in place)
    float* Vr = smf + 2 * 64 * SK;    // 1 stage  x 64 x SK (raw)
    float* Vt = smf + 3 * 64 * SK;    // 64 ch x SK (transposed, key-permuted)
    float* Ps = smf + 4 * 64 * SK;    // 128 q x SK (Q staging, then P)

    int qp = blockIdx.x >> 2, kvq = blockIdx.x & 3;
    int head = blockIdx.y, bb = blockIdx.z;
    int bhi = bb * NH + head;
    int tid = threadIdx.x;
    int w = tid >> 5, l = tid & 31;
    int la = l >> 2, lb = l & 3;

    uint32_t kr_u = (uint32_t)__cvta_generic_to_shared(Kr);
    uint32_t vr_u = (uint32_t)__cvta_generic_to_shared(Vr);

    auto src_ptr = [&](const float* cache, const float* cur, int i) -> const float* {
        int ktg = kvq * ITERS + i;
        int t = ktg >> 2, st = ktg & 3;
        if (t < TCACHE)
            return cache + ((((size_t)bhi * TCACHE + t) * HW + st * 64)) * CH;
        return cur + (((size_t)bhi * HW + st * 64)) * CH;
    };

    int krow = tid >> 1, half = tid & 1;

    auto issue_k = [&](int i) {
        const float* kp = src_ptr(ck, g_k, i);
        int s = i & 1;
        uint32_t kd = kr_u + (uint32_t)(s * 64 * SK + krow * SK + half * 32) * 4u;
        const float* ks = kp + krow * CH + half * 32;
#pragma unroll
        for (int c = 0; c < 8; c++) cpa16(kd + c * 16, ks + c * 4);
    };
    auto issue_v = [&](int i) {
        const float* vp = src_ptr(cv, g_v, i);
        uint32_t vd = vr_u + (uint32_t)(krow * SK + half * 32) * 4u;
        const float* vs = vp + krow * CH + half * 32;
#pragma unroll
        for (int c = 0; c < 8; c++) cpa16(vd + c * 16, vs + c * 4);
    };

    // group order: {K0,V0}, {K1}, then per-iter mid {V(i+1)}, end {K(i+2)}
    issue_k(0); issue_v(0); CP_COMMIT();
    issue_k(1); CP_COMMIT();

    // -------- stage Q: rope(pos 63), * log2e/8, tf32, permuted --------
    {
        int r = tid;
        const float* qpv = g_q + (((size_t)bhi) * HW + qp * 128 + r) * CH;
        const float2* tq = g_rope + 63 * 32;
        const float sc = 0.125f * LOG2E;
        unsigned* pr = reinterpret_cast<unsigned*>(Ps + r * SK);
#pragma unroll
        for (int g = 0; g < 8; g++) {
            float4 x0 = *reinterpret_cast<const float4*>(qpv + 8 * g);
            float4 x1 = *reinterpret_cast<const float4*>(qpv + 8 * g + 4);
            float2 t0 = tq[4 * g], t1 = tq[4 * g + 1], t2 = tq[4 * g + 2], t3 = tq[4 * g + 3];
            float l0 = (x0.x * t0.x - x0.y * t0.y) * sc;
            float l1 = (x0.x * t0.y + x0.y * t0.x) * sc;
            float l2 = (x0.z * t1.x - x0.w * t1.y) * sc;
            float l3 = (x0.z * t1.y + x0.w * t1.x) * sc;
            float l4 = (x1.x * t2.x - x1.y * t2.y) * sc;
            float l5 = (x1.x * t2.y + x1.y * t2.x) * sc;
            float l6 = (x1.z * t3.x - x1.w * t3.y) * sc;
            float l7 = (x1.z * t3.y + x1.w * t3.x) * sc;
            pr[8 * g + 0] = f2tf(l0); pr[8 * g + 1] = f2tf(l4);
            pr[8 * g + 2] = f2tf(l1); pr[8 * g + 3] = f2tf(l5);
            pr[8 * g + 4] = f2tf(l2); pr[8 * g + 5] = f2tf(l6);
            pr[8 * g + 6] = f2tf(l3); pr[8 * g + 7] = f2tf(l7);
        }
    }
    __syncthreads();

    // -------- Q fragments: warp w owns rows {16w..16w+15} of both 64-row tiles --------
    unsigned qa[2][8][4];
#pragma unroll
    for (int tt = 0; tt < 2; tt++) {
        int r0 = tt * 64 + 16 * w + la;
#pragma unroll
        for (int kk = 0; kk < 8; kk++) {
            uint2 p0 = *reinterpret_cast<const uint2*>(&Ps[r0 * SK + kk * 8 + 2 * lb]);
            uint2 p1 = *reinterpret_cast<const uint2*>(&Ps[(r0 + 8) * SK + kk * 8 + 2 * lb]);
            qa[tt][kk][0] = p0.x; qa[tt][kk][1] = p1.x; qa[tt][kk][2] = p0.y; qa[tt][kk][3] = p1.y;
        }
    }
    __syncthreads();

    float oacc[2][8][4] = {};
    float rm[2][2] = {{-1e30f, -1e30f}, {-1e30f, -1e30f}};
    float ls[2][2] = {};
    const int P0 = pc8(2 * lb), P1 = pc8(2 * lb + 1);
    const int pkey = 16 * w + la;

    for (int i = 0; i < ITERS; i++) {
        int s = i & 1;
        CP_WAIT1();      // K(i), V(i) arrived (next K group may be in flight)
        __syncthreads();

        // ---- convert: K rope+permute in place; V transpose+permute into Vt ----
        {
            int t = (kvq * ITERS + i) >> 2;
            float* kb = Kr + s * 64 * SK + krow * SK;
            const float2* tt_ = g_rope + t * 32 + half * 16;
#pragma unroll
            for (int g2 = 0; g2 < 4; g2++) {
                int ch0 = (half * 4 + g2) * 8;
                float4 a = *reinterpret_cast<const float4*>(kb + ch0);
                float4 b = *reinterpret_cast<const float4*>(kb + ch0 + 4);
                float2 t0 = tt_[4 * g2], t1 = tt_[4 * g2 + 1], t2 = tt_[4 * g2 + 2], t3 = tt_[4 * g2 + 3];
                float l0 = a.x * t0.x - a.y * t0.y;
                float l1 = a.x * t0.y + a.y * t0.x;
                float l2 = a.z * t1.x - a.w * t1.y;
                float l3 = a.z * t1.y + a.w * t1.x;
                float l4 = b.x * t2.x - b.y * t2.y;
                float l5 = b.x * t2.y + b.y * t2.x;
                float l6 = b.z * t3.x - b.w * t3.y;
                float l7 = b.z * t3.y + b.w * t3.x;
                unsigned* o = reinterpret_cast<unsigned*>(kb + ch0);
                o[0] = f2tf(l0); o[1] = f2tf(l4); o[2] = f2tf(l1); o[3] = f2tf(l5);
                o[4] = f2tf(l2); o[5] = f2tf(l6); o[6] = f2tf(l3); o[7] = f2tf(l7);
            }
            float* vb = Vr + krow * SK;
            int pk = (krow & ~7) | pc8(krow & 7);
            unsigned* vt = reinterpret_cast<unsigned*>(Vt);
#pragma unroll
            for (int c = 0; c < 8; c++) {
                int ch0 = half * 32 + c * 4;
                float4 v = *reinterpret_cast<const float4*>(vb + ch0);
                vt[(ch0 + 0) * SK + pk] = f2tf(v.x);
                vt[(ch0 + 1) * SK + pk] = f2tf(v.y);
                vt[(ch0 + 2) * SK + pk] = f2tf(v.z);
                vt[(ch0 + 3) * SK + pk] = f2tf(v.w);
            }
        }
        __syncthreads();

        // Vr raw is free now: prefetch V(i+1)
        if (i + 1 < ITERS) issue_v(i + 1);
        CP_COMMIT();

        // ---- per q-tile: S = QK^T, online softmax, P store ----
        const float* Kb = Kr + s * 64 * SK;
#pragma unroll
        for (int tt = 0; tt < 2; tt++) {
            float sc[8][4];
#pragma unroll
            for (int nn = 0; nn < 8; nn++) {
                sc[nn][0] = sc[nn][1] = sc[nn][2] = sc[nn][3] = 0.f;
                const float* kr = Kb + (nn * 8 + la) * SK;
#pragma unroll
                for (int kk = 0; kk < 8; kk++) {
                    uint2 b = *reinterpret_cast<const uint2*>(kr + kk * 8 + 2 * lb);
                    mma8(sc[nn], qa[tt][kk], b.x, b.y);
                }
            }
            float mx0 = -1e30f, mx1 = -1e30f;
#pragma unroll
            for (int nn = 0; nn < 8; nn++) {
                mx0 = fmaxf(mx0, fmaxf(sc[nn][0], sc[nn][1]));
                mx1 = fmaxf(mx1, fmaxf(sc[nn][2], sc[nn][3]));
            }
            mx0 = fmaxf(mx0, __shfl_xor_sync(0xffffffffu, mx0, 1));
            mx0 = fmaxf(mx0, __shfl_xor_sync(0xffffffffu, mx0, 2));
            mx1 = fmaxf(mx1, __shfl_xor_sync(0xffffffffu, mx1, 1));
            mx1 = fmaxf(mx1, __shfl_xor_sync(0xffffffffu, mx1, 2));
            float mn0 = fmaxf(rm[tt][0], mx0), mn1 = fmaxf(rm[tt][1], mx1);
            float al0 = ex2(rm[tt][0] - mn0), al1 = ex2(rm[tt][1] - mn1);
            float s0 = 0.f, s1 = 0.f;
            float* pr0 = Ps + (tt * 64 + pkey) * SK;
            float* pr1 = Ps + (tt * 64 + pkey + 8) * SK;
#pragma unroll
            for (int nn = 0; nn < 8; nn++) {
                float p0 = ex2(sc[nn][0] - mn0);
                float p1 = ex2(sc[nn][1] - mn0);
                float p2 = ex2(sc[nn][2] - mn1);
                float p3 = ex2(sc[nn][3] - mn1);
                s0 += p0 + p1; s1 += p2 + p3;
                pr0[nn * 8 + P0] = p0;   // raw f32 bits; HW truncates to tf32
                pr0[nn * 8 + P1] = p1;
                pr1[nn * 8 + P0] = p2;
                pr1[nn * 8 + P1] = p3;
            }
            s0 += __shfl_xor_sync(0xffffffffu, s0, 1);
            s0 += __shfl_xor_sync(0xffffffffu, s0, 2);
            s1 += __shfl_xor_sync(0xffffffffu, s1, 1);
            s1 += __shfl_xor_sync(0xffffffffu, s1, 2);
            ls[tt][0] = ls[tt][0] * al0 + s0;
            ls[tt][1] = ls[tt][1] * al1 + s1;
            rm[tt][0] = mn0; rm[tt][1] = mn1;
#pragma unroll
            for (int nn = 0; nn < 8; nn++) {
                oacc[tt][nn][0] *= al0; oacc[tt][nn][1] *= al0;
                oacc[tt][nn][2] *= al1; oacc[tt][nn][3] *= al1;
            }
        }
        __syncwarp();  // P rows are warp-private

        // ---- O += P V (V-frags shared across both q-tiles) ----
#pragma unroll
        for (int kk = 0; kk < 8; kk++) {
            uint2 a0l = *reinterpret_cast<const uint2*>(&Ps[pkey * SK + kk * 8 + 2 * lb]);
            uint2 a0h = *reinterpret_cast<const uint2*>(&Ps[(pkey + 8) * SK + kk * 8 + 2 * lb]);
            uint2 a1l = *reinterpret_cast<const uint2*>(&Ps[(64 + pkey) * SK + kk * 8 + 2 * lb]);
            uint2 a1h = *reinterpret_cast<const uint2*>(&Ps[(64 + pkey + 8) * SK + kk * 8 + 2 * lb]);
            unsigned A0[4] = {a0l.x, a0h.x, a0l.y, a0h.y};
            unsigned A1[4] = {a1l.x, a1h.x, a1l.y, a1h.y};
#pragma unroll
            for (int nn = 0; nn < 8; nn++) {
                uint2 b = *reinterpret_cast<const uint2*>(&Vt[(nn * 8 + la) * SK + kk * 8 + 2 * lb]);
                mma8(oacc[0][nn], A0, b.x, b.y);
                mma8(oacc[1][nn], A1, b.x, b.y);
            }
        }

        __syncthreads();            // all reads of Kr stage s done before overwrite
        if (i + 2 < ITERS) issue_k(i + 2);
        CP_COMMIT();
    }

    // -------- epilogue: write split-KV partials --------
    int pbase = ((bhi * 2 + qp) * NKV + kvq);
    float* po = g_po + (size_t)pbase * 8192;
#pragma unroll
    for (int tt = 0; tt < 2; tt++) {
        int row = tt * 64 + pkey;
#pragma unroll
        for (int nn = 0; nn < 8; nn++) {
            int ch = nn * 8 + 2 * lb;
            po[(ch + 0) * 128 + row]     = oacc[tt][nn][0];
            po[(ch + 1) * 128 + row]     = oacc[tt][nn][1];
            po[(ch + 0) * 128 + row + 8] = oacc[tt][nn][2];
            po[(ch + 1) * 128 + row + 8] = oacc[tt][nn][3];
        }
        if (lb == 0) {
            g_pm[pbase * 128 + row]     = rm[tt][0];
            g_pl[pbase * 128 + row]     = ls[tt][0];
            g_pm[pbase * 128 + row + 8] = rm[tt][1];
            g_pl[pbase * 128 + row + 8] = ls[tt][1];
        }
    }
}

// ---------------- K3b: split-KV combine (4 partials) -> g_o ----------------
__global__ __launch_bounds__(256) void combine_kernel() {
    int qp = blockIdx.x, head = blockIdx.y, bb = blockIdx.z;
    int pb = (((bb * NH + head) * 2 + qp) * NKV);
    int tid = threadIdx.x;
    __shared__ float ws[NKV][128], il[128];
    if (tid < 128) {
        float m[NKV], lv[NKV];
        float M = -1e30f;
#pragma unroll
        for (int k = 0; k < NKV; k++) {
            m[k] = g_pm[(pb + k) * 128 + tid];
            lv[k] = g_pl[(pb + k) * 128 + tid];
            M = fmaxf(M, m[k]);
        }
        float den = 0.f;
#pragma unroll
        for (int k = 0; k < NKV; k++) {
            float wv = ex2(m[k] - M);
            ws[k][tid] = wv;
            den += wv * lv[k];
        }
        il[tid] = 1.0f / den;
    }
    __syncthreads();
    int ch = tid >> 2, sg = tid & 3;
    float* dst = g_o + ((size_t)bb * CDIM + (ch * NH + head)) * HW + qp * 128;
#pragma unroll 4
    for (int rr = 0; rr < 32; rr++) {
        int r = sg * 32 + rr;
        float acc = 0.f;
#pragma unroll
        for (int k = 0; k < NKV; k++)
            acc += ws[k][r] * g_po[(size_t)(pb + k) * 8192 + ch * 128 + r];
        dst[r] = acc * il[r];
    }
}

// ---------------- K4: proj GEMM + mp_sum ----------------
__global__ __launch_bounds__(256) void proj_kernel(const float* __restrict__ x,
                                                   float* __restrict__ out) {
    __shared__ float As[16][68];
    __shared__ float Bs[16][68];
    int bb = blockIdx.z;
    int m0 = blockIdx.y * 64;
    int n0 = blockIdx.x * 64;
    int tid = threadIdx.x;
    int ty = tid >> 4, tx = tid & 15;
    float acc[4][4] = {};

    for (int k0 = 0; k0 < CDIM; k0 += 16) {
        {
            int lin = tid * 4;
            int mi = lin >> 4, ki = lin & 15;
            float4 a = *reinterpret_cast<const float4*>(&g_wproj_n[(size_t)(m0 + mi) * CDIM + k0 + ki]);
            As[ki + 0][mi] = a.x; As[ki + 1][mi] = a.y; As[ki + 2][mi] = a.z; As[ki + 3][mi] = a.w;
        }
        {
            int lin = tid * 4;
            int ki = lin >> 6, ni = lin & 63;
            float4 b = *reinterpret_cast<const float4*>(&g_o[((size_t)bb * CDIM + k0 + ki) * HW + n0 + ni]);
            *reinterpret_cast<float4*>(&Bs[ki][ni]) = b;
        }
        __syncthreads();
#pragma unroll
        for (int kk = 0; kk < 16; kk++) {
            float4 a = *reinterpret_cast<const float4*>(&As[kk][ty * 4]);
            float4 b = *reinterpret_cast<const float4*>(&Bs[kk][tx * 4]);
            float av[4] = {a.x, a.y, a.z, a.w};
            float bv[4] = {b.x, b.y, b.z, b.w};
#pragma unroll
            for (int i = 0; i < 4; i++)
#pragma unroll
                for (int j = 0; j < 4; j++) acc[i][j] += av[i] * bv[j];
        }
        __syncthreads();
    }

    const float norm = 1.3130643286f;  // 1/sqrt(0.7^2+0.3^2)
#pragma unroll
    for (int i = 0; i < 4; i++) {
        int och = m0 + ty * 4 + i;
#pragma unroll
        for (int j = 0; j < 4; j++) {
            int s = n0 + tx * 4 + j;
            size_t idx = ((size_t)bb * CDIM + och) * HW + s;
            out[idx] = (0.7f * x[idx] + 0.3f * acc[i][j]) * norm;
        }
    }
}

extern "C" void kernel_launch(void* const* d_in, const int* in_sizes, int n_in,
                              void* d_out, int out_size) {
    const float* x     = (const float*)d_in[0];
    const float* ck    = (const float*)d_in[1];
    const float* cv    = (const float*)d_in[2];
    const float* wqkv  = (const float*)d_in[3];
    const float* wproj = (const float*)d_in[4];
    float* out = (float*)d_out;

    norm_kernel<<<4 * CDIM, 128>>>(wqkv, wproj);
    rope_table_kernel<<<8, 256>>>();
    qkv_gemm_kernel<<<dim3(4, 24, 4), 256>>>(x);

    int smem = 6 * 64 * SK * (int)sizeof(float);  // 110592 B -> 2 CTAs/SM
    cudaFuncSetAttribute(attn_kernel, cudaFuncAttributeMaxDynamicSharedMemorySize, smem);
    attn_kernel<<<dim3(8, NH, 4), 128, smem>>>(ck, cv);

    combine_kernel<<<dim3(2, NH, BATCH), 256>>>();
    proj_kernel<<<dim3(4, 8, 4), 256>>>(x, out);
}

// round 9
// speedup vs baseline: 1.7264x; 1.1358x over previous
#include <cuda_runtime.h>
#include <math.h>
#include <stdint.h>

#define NH 8
#define CDIM 512
#define HW 256
#define CH 64
#define BATCH 4
#define TCACHE 63
#define SK 72                 // smem row stride (words)
#define NKV 4                 // KV split factor
#define ITERS 64              // 256 subtiles / NKV
#define LOG2E 1.4426950408889634f

__device__ float g_wqkv_n[3 * CDIM * CDIM];
__device__ float g_wproj_n[CDIM * CDIM];
__device__ float2 g_rope[64 * 32];          // {cos,sin}[t][j]
__device__ float g_q[BATCH * NH * HW * CH];
__device__ float g_k[BATCH * NH * HW * CH];
__device__ float g_v[BATCH * NH * HW * CH];
__device__ float g_o[BATCH * CDIM * HW];    // [b][ch*NH+head][s]
// split-KV partials: [(((b*8+h)*2+qp)*NKV+kvq)] x [ch 64][row 128]
__device__ float g_po[BATCH * NH * 2 * NKV * 64 * 128];
__device__ float g_pl[BATCH * NH * 2 * NKV * 128];

__device__ __forceinline__ unsigned f2tf(float x) {
    unsigned r;
    asm("cvt.rna.tf32.f32 %0, %1;" : "=r"(r) : "f"(x));
    return r;
}
__device__ __forceinline__ float ex2(float x) {
    float y;
    asm("ex2.approx.f32 %0, %1;" : "=f"(y) : "f"(x));
    return y;
}
__device__ __forceinline__ void mma8(float c[4], const unsigned a[4], unsigned b0, unsigned b1) {
    asm volatile(
        "mma.sync.aligned.m16n8k8.row.col.f32.tf32.tf32.f32 "
        "{%0,%1,%2,%3}, {%4,%5,%6,%7}, {%8,%9}, {%0,%1,%2,%3};\n"
        : "+f"(c[0]), "+f"(c[1]), "+f"(c[2]), "+f"(c[3])
        : "r"(a[0]), "r"(a[1]), "r"(a[2]), "r"(a[3]), "r"(b0), "r"(b1));
}
// logical r (0..7) in an 8-group -> physical slot so frag pair (r, r+4) is adjacent
__device__ __forceinline__ int pc8(int r) { return ((r & 3) << 1) | (r >> 2); }

__device__ __forceinline__ void cpa16(uint32_t dst, const void* src) {
    asm volatile("cp.async.cg.shared.global [%0], [%1], 16;" :: "r"(dst), "l"(src));
}
#define CP_COMMIT() asm volatile("cp.async.commit_group;")
#define CP_WAIT1()  asm volatile("cp.async.wait_group 1;")

// ---------------- K1a: mp_weight row normalization ----------------
__global__ void norm_kernel(const float* __restrict__ wq, const float* __restrict__ wp) {
    int r = blockIdx.x;
    const float* src;
    float* dst;
    if (r < 3 * CDIM) { src = wq + (size_t)r * CDIM; dst = g_wqkv_n + (size_t)r * CDIM; }
    else { int rr = r - 3 * CDIM; src = wp + (size_t)rr * CDIM; dst = g_wproj_n + (size_t)rr * CDIM; }

    float4 v = reinterpret_cast<const float4*>(src)[threadIdx.x];
    float ss = v.x * v.x + v.y * v.y + v.z * v.z + v.w * v.w;
    for (int o = 16; o; o >>= 1) ss += __shfl_xor_sync(0xffffffffu, ss, o);
    __shared__ float wsum[4];
    if ((threadIdx.x & 31) == 0) wsum[threadIdx.x >> 5] = ss;
    __syncthreads();
    float nrm = sqrtf(wsum[0] + wsum[1] + wsum[2] + wsum[3]);
    float s512 = sqrtf((float)CDIM);
    float scale = 1.0f / ((1e-4f + nrm / s512) * s512);
    float4 o4;
    o4.x = v.x * scale; o4.y = v.y * scale; o4.z = v.z * scale; o4.w = v.w * scale;
    reinterpret_cast<float4*>(dst)[threadIdx.x] = o4;
}

// ---------------- K1b: rope table ----------------
__global__ void rope_table_kernel() {
    int idx = blockIdx.x * blockDim.x + threadIdx.x;
    if (idx < 64 * 32) {
        int t = idx >> 5, j = idx & 31;
        float inv = powf(10000.0f, -(2.0f * (float)j) / 64.0f);
        float a = (float)t * inv;
        g_rope[idx] = make_float2(cosf(a), sinf(a));
    }
}

// ---------------- K2: QKV GEMM (fp32) -> q/k/v [b][head][s][ch] ----------------
__global__ __launch_bounds__(256) void qkv_gemm_kernel(const float* __restrict__ x) {
    __shared__ float As[16][68];
    __shared__ float Bs[16][68];
    int bb = blockIdx.z;
    int m0 = blockIdx.y * 64;
    int n0 = blockIdx.x * 64;
    int tid = threadIdx.x;
    int ty = tid >> 4, tx = tid & 15;
    float acc[4][4] = {};

    for (int k0 = 0; k0 < CDIM; k0 += 16) {
        {
            int lin = tid * 4;
            int mi = lin >> 4, ki = lin & 15;
            float4 a = *reinterpret_cast<const float4*>(&g_wqkv_n[(size_t)(m0 + mi) * CDIM + k0 + ki]);
            As[ki + 0][mi] = a.x; As[ki + 1][mi] = a.y; As[ki + 2][mi] = a.z; As[ki + 3][mi] = a.w;
        }
        {
            int lin = tid * 4;
            int ki = lin >> 6, ni = lin & 63;
            float4 b = *reinterpret_cast<const float4*>(&x[((size_t)bb * CDIM + k0 + ki) * HW + n0 + ni]);
            *reinterpret_cast<float4*>(&Bs[ki][ni]) = b;
        }
        __syncthreads();
#pragma unroll
        for (int kk = 0; kk < 16; kk++) {
            float4 a = *reinterpret_cast<const float4*>(&As[kk][ty * 4]);
            float4 b = *reinterpret_cast<const float4*>(&Bs[kk][tx * 4]);
            float av[4] = {a.x, a.y, a.z, a.w};
            float bv[4] = {b.x, b.y, b.z, b.w};
#pragma unroll
            for (int i = 0; i < 4; i++)
#pragma unroll
                for (int j = 0; j < 4; j++) acc[i][j] += av[i] * bv[j];
        }
        __syncthreads();
    }

    int which = m0 >> 9;
    int head = (m0 >> 6) & 7;
    float* dst = (which == 0) ? g_q : ((which == 1) ? g_k : g_v);
#pragma unroll
    for (int i = 0; i < 4; i++) {
        int ch = ty * 4 + i;
#pragma unroll
        for (int j = 0; j < 4; j++) {
            int s = n0 + tx * 4 + j;
            dst[(((size_t)bb * NH + head) * HW + s) * CH + ch] = acc[i][j];
        }
    }
}

// ---------------- K3: flash attention v5 ----------------
// 128 thr, 2 q-tiles/warp, 4-way KV split, P-in-registers, fixed-max softmax.
// grid (8, 8, 4): x -> qp = x>>2 (128-q-row block), kvq = x&3 (64-iter KV quarter)
__global__ __launch_bounds__(128, 2) void attn_kernel(const float* __restrict__ ck,
                                                      const float* __restrict__ cv) {
    extern __shared__ float smf[];
    float* Kr = smf;                  // 2 stages x 64 x SK (K; rows stored key-permuted) | prologue: Q staging 128 x SK
    float* Vr = smf + 2 * 64 * SK;    // raw V landing
    float* Vt = smf + 3 * 64 * SK;    // 64 ch x SK (transposed, key-permuted)

    int qp = blockIdx.x >> 2, kvq = blockIdx.x & 3;
    int head = blockIdx.y, bb = blockIdx.z;
    int bhi = bb * NH + head;
    int tid = threadIdx.x;
    int w = tid >> 5, l = tid & 31;
    int la = l >> 2, lb = l & 3;

    uint32_t kr_u = (uint32_t)__cvta_generic_to_shared(Kr);
    uint32_t vr_u = (uint32_t)__cvta_generic_to_shared(Vr);

    auto src_ptr = [&](const float* cache, const float* cur, int i) -> const float* {
        int ktg = kvq * ITERS + i;
        int t = ktg >> 2, st = ktg & 3;
        if (t < TCACHE)
            return cache + ((((size_t)bhi * TCACHE + t) * HW + st * 64)) * CH;
        return cur + (((size_t)bhi * HW + st * 64)) * CH;
    };

    int krow = tid >> 1, half = tid & 1;
    int krow_p = (krow & ~7) | pc8(krow & 7);   // permuted K row position

    auto issue_k = [&](int i) {
        const float* kp = src_ptr(ck, g_k, i);
        int s = i & 1;
        uint32_t kd = kr_u + (uint32_t)(s * 64 * SK + krow_p * SK + half * 32) * 4u;
        const float* ks = kp + krow * CH + half * 32;
#pragma unroll
        for (int c = 0; c < 8; c++) cpa16(kd + c * 16, ks + c * 4);
    };
    auto issue_v = [&](int i) {
        const float* vp = src_ptr(cv, g_v, i);
        uint32_t vd = vr_u + (uint32_t)(krow * SK + half * 32) * 4u;
        const float* vs = vp + krow * CH + half * 32;
#pragma unroll
        for (int c = 0; c < 8; c++) cpa16(vd + c * 16, vs + c * 4);
    };

    // -------- prologue: stage Q into Kr region (before any cp.async touches it) ----
    {
        int r = tid;
        const float* qpv = g_q + (((size_t)bhi) * HW + qp * 128 + r) * CH;
        const float2* tq = g_rope + 63 * 32;
        const float sc = 0.125f * LOG2E;
        unsigned* pr = reinterpret_cast<unsigned*>(Kr + r * SK);
#pragma unroll
        for (int g = 0; g < 8; g++) {
            float4 x0 = *reinterpret_cast<const float4*>(qpv + 8 * g);
            float4 x1 = *reinterpret_cast<const float4*>(qpv + 8 * g + 4);
            float2 t0 = tq[4 * g], t1 = tq[4 * g + 1], t2 = tq[4 * g + 2], t3 = tq[4 * g + 3];
            float l0 = (x0.x * t0.x - x0.y * t0.y) * sc;
            float l1 = (x0.x * t0.y + x0.y * t0.x) * sc;
            float l2 = (x0.z * t1.x - x0.w * t1.y) * sc;
            float l3 = (x0.z * t1.y + x0.w * t1.x) * sc;
            float l4 = (x1.x * t2.x - x1.y * t2.y) * sc;
            float l5 = (x1.x * t2.y + x1.y * t2.x) * sc;
            float l6 = (x1.z * t3.x - x1.w * t3.y) * sc;
            float l7 = (x1.z * t3.y + x1.w * t3.x) * sc;
            pr[8 * g + 0] = f2tf(l0); pr[8 * g + 1] = f2tf(l4);
            pr[8 * g + 2] = f2tf(l1); pr[8 * g + 3] = f2tf(l5);
            pr[8 * g + 4] = f2tf(l2); pr[8 * g + 5] = f2tf(l6);
            pr[8 * g + 6] = f2tf(l3); pr[8 * g + 7] = f2tf(l7);
        }
    }
    __syncthreads();

    unsigned qa[2][8][4];
#pragma unroll
    for (int tt = 0; tt < 2; tt++) {
        int r0 = tt * 64 + 16 * w + la;
#pragma unroll
        for (int kk = 0; kk < 8; kk++) {
            uint2 p0 = *reinterpret_cast<const uint2*>(&Kr[r0 * SK + kk * 8 + 2 * lb]);
            uint2 p1 = *reinterpret_cast<const uint2*>(&Kr[(r0 + 8) * SK + kk * 8 + 2 * lb]);
            qa[tt][kk][0] = p0.x; qa[tt][kk][1] = p1.x; qa[tt][kk][2] = p0.y; qa[tt][kk][3] = p1.y;
        }
    }
    __syncthreads();

    // now safe to start the cp.async pipeline into Kr
    issue_k(0); issue_v(0); CP_COMMIT();
    issue_k(1); CP_COMMIT();

    float oacc[2][8][4] = {};
    float ls[2][2] = {};

    for (int i = 0; i < ITERS; i++) {
        int s = i & 1;
        CP_WAIT1();      // K(i), V(i) arrived
        __syncthreads();

        // ---- convert: K rope+ch-permute in place; V transpose+key-permute into Vt ----
        {
            int t = (kvq * ITERS + i) >> 2;
            float* kb = Kr + s * 64 * SK + krow_p * SK;
            const float2* tt_ = g_rope + t * 32 + half * 16;
#pragma unroll
            for (int g2 = 0; g2 < 4; g2++) {
                int ch0 = (half * 4 + g2) * 8;
                float4 a = *reinterpret_cast<const float4*>(kb + ch0);
                float4 b = *reinterpret_cast<const float4*>(kb + ch0 + 4);
                float2 t0 = tt_[4 * g2], t1 = tt_[4 * g2 + 1], t2 = tt_[4 * g2 + 2], t3 = tt_[4 * g2 + 3];
                float l0 = a.x * t0.x - a.y * t0.y;
                float l1 = a.x * t0.y + a.y * t0.x;
                float l2 = a.z * t1.x - a.w * t1.y;
                float l3 = a.z * t1.y + a.w * t1.x;
                float l4 = b.x * t2.x - b.y * t2.y;
                float l5 = b.x * t2.y + b.y * t2.x;
                float l6 = b.z * t3.x - b.w * t3.y;
                float l7 = b.z * t3.y + b.w * t3.x;
                unsigned* o = reinterpret_cast<unsigned*>(kb + ch0);
                o[0] = f2tf(l0); o[1] = f2tf(l4); o[2] = f2tf(l1); o[3] = f2tf(l5);
                o[4] = f2tf(l2); o[5] = f2tf(l6); o[6] = f2tf(l3); o[7] = f2tf(l7);
            }
            float* vb = Vr + krow * SK;
            unsigned* vt = reinterpret_cast<unsigned*>(Vt);
#pragma unroll
            for (int c = 0; c < 8; c++) {
                int ch0 = half * 32 + c * 4;
                float4 v = *reinterpret_cast<const float4*>(vb + ch0);
                vt[(ch0 + 0) * SK + krow_p] = f2tf(v.x);
                vt[(ch0 + 1) * SK + krow_p] = f2tf(v.y);
                vt[(ch0 + 2) * SK + krow_p] = f2tf(v.z);
                vt[(ch0 + 3) * SK + krow_p] = f2tf(v.w);
            }
        }
        __syncthreads();

        // Vr raw free: prefetch V(i+1)
        if (i + 1 < ITERS) issue_v(i + 1);
        CP_COMMIT();

        // ---- per q-tile: S = QK^T -> P=exp2 in regs -> O += P V ----
        const float* Kb = Kr + s * 64 * SK;
#pragma unroll
        for (int tt = 0; tt < 2; tt++) {
            float sc[8][4];
#pragma unroll
            for (int nn = 0; nn < 8; nn++) {
                sc[nn][0] = sc[nn][1] = sc[nn][2] = sc[nn][3] = 0.f;
                const float* kr = Kb + (nn * 8 + la) * SK;
#pragma unroll
                for (int kk = 0; kk < 8; kk++) {
                    uint2 b = *reinterpret_cast<const uint2*>(kr + kk * 8 + 2 * lb);
                    mma8(sc[nn], qa[tt][kk], b.x, b.y);
                }
            }
            // P = exp2(S) directly into A-fragments (c0,c2,c1,c3 reorder)
            unsigned pa[8][4];
            float s0 = 0.f, s1 = 0.f;
#pragma unroll
            for (int nn = 0; nn < 8; nn++) {
                float p0 = ex2(sc[nn][0]);
                float p1 = ex2(sc[nn][1]);
                float p2 = ex2(sc[nn][2]);
                float p3 = ex2(sc[nn][3]);
                s0 += p0 + p1; s1 += p2 + p3;
                pa[nn][0] = __float_as_uint(p0);  // (la,   k=lb)
                pa[nn][1] = __float_as_uint(p2);  // (la+8, k=lb)
                pa[nn][2] = __float_as_uint(p1);  // (la,   k=lb+4)
                pa[nn][3] = __float_as_uint(p3);  // (la+8, k=lb+4)
            }
            s0 += __shfl_xor_sync(0xffffffffu, s0, 1);
            s0 += __shfl_xor_sync(0xffffffffu, s0, 2);
            s1 += __shfl_xor_sync(0xffffffffu, s1, 1);
            s1 += __shfl_xor_sync(0xffffffffu, s1, 2);
            ls[tt][0] += s0;
            ls[tt][1] += s1;
#pragma unroll
            for (int kk = 0; kk < 8; kk++) {
#pragma unroll
                for (int nn = 0; nn < 8; nn++) {
                    uint2 b = *reinterpret_cast<const uint2*>(&Vt[(nn * 8 + la) * SK + kk * 8 + 2 * lb]);
                    mma8(oacc[tt][nn], pa[kk], b.x, b.y);
                }
            }
        }

        __syncthreads();            // all reads of Kr stage s done before overwrite
        if (i + 2 < ITERS) issue_k(i + 2);
        CP_COMMIT();
    }

    // -------- epilogue: write split-KV partials (fixed max: just O and l) --------
    int pbase = ((bhi * 2 + qp) * NKV + kvq);
    float* po = g_po + (size_t)pbase * 8192;
    int prow = 16 * w + la;
#pragma unroll
    for (int tt = 0; tt < 2; tt++) {
        int row = tt * 64 + prow;
#pragma unroll
        for (int nn = 0; nn < 8; nn++) {
            int ch = nn * 8 + 2 * lb;
            po[(ch + 0) * 128 + row]     = oacc[tt][nn][0];
            po[(ch + 1) * 128 + row]     = oacc[tt][nn][1];
            po[(ch + 0) * 128 + row + 8] = oacc[tt][nn][2];
            po[(ch + 1) * 128 + row + 8] = oacc[tt][nn][3];
        }
        if (lb == 0) {
            g_pl[pbase * 128 + row]     = ls[tt][0];
            g_pl[pbase * 128 + row + 8] = ls[tt][1];
        }
    }
}

// ---------------- K3b: split-KV combine (sum of partials) -> g_o ----------------
__global__ __launch_bounds__(256) void combine_kernel() {
    int qp = blockIdx.x, head = blockIdx.y, bb = blockIdx.z;
    int pb = (((bb * NH + head) * 2 + qp) * NKV);
    int tid = threadIdx.x;
    __shared__ float il[128];
    if (tid < 128) {
        float den = 0.f;
#pragma unroll
        for (int k = 0; k < NKV; k++) den += g_pl[(pb + k) * 128 + tid];
        il[tid] = 1.0f / den;
    }
    __syncthreads();
    int ch = tid >> 2, sg = tid & 3;
    float* dst = g_o + ((size_t)bb * CDIM + (ch * NH + head)) * HW + qp * 128;
#pragma unroll 4
    for (int rr = 0; rr < 32; rr++) {
        int r = sg * 32 + rr;
        float acc = 0.f;
#pragma unroll
        for (int k = 0; k < NKV; k++)
            acc += g_po[(size_t)(pb + k) * 8192 + ch * 128 + r];
        dst[r] = acc * il[r];
    }
}

// ---------------- K4: proj GEMM + mp_sum ----------------
__global__ __launch_bounds__(256) void proj_kernel(const float* __restrict__ x,
                                                   float* __restrict__ out) {
    __shared__ float As[16][68];
    __shared__ float Bs[16][68];
    int bb = blockIdx.z;
    int m0 = blockIdx.y * 64;
    int n0 = blockIdx.x * 64;
    int tid = threadIdx.x;
    int ty = tid >> 4, tx = tid & 15;
    float acc[4][4] = {};

    for (int k0 = 0; k0 < CDIM; k0 += 16) {
        {
            int lin = tid * 4;
            int mi = lin >> 4, ki = lin & 15;
            float4 a = *reinterpret_cast<const float4*>(&g_wproj_n[(size_t)(m0 + mi) * CDIM + k0 + ki]);
            As[ki + 0][mi] = a.x; As[ki + 1][mi] = a.y; As[ki + 2][mi] = a.z; As[ki + 3][mi] = a.w;
        }
        {
            int lin = tid * 4;
            int ki = lin >> 6, ni = lin & 63;
            float4 b = *reinterpret_cast<const float4*>(&g_o[((size_t)bb * CDIM + k0 + ki) * HW + n0 + ni]);
            *reinterpret_cast<float4*>(&Bs[ki][ni]) = b;
        }
        __syncthreads();
#pragma unroll
        for (int kk = 0; kk < 16; kk++) {
            float4 a = *reinterpret_cast<const float4*>(&As[kk][ty * 4]);
            float4 b = *reinterpret_cast<const float4*>(&Bs[kk][tx * 4]);
            float av[4] = {a.x, a.y, a.z, a.w};
            float bv[4] = {b.x, b.y, b.z, b.w};
#pragma unroll
            for (int i = 0; i < 4; i++)
#pragma unroll
                for (int j = 0; j < 4; j++) acc[i][j] += av[i] * bv[j];
        }
        __syncthreads();
    }

    const float norm = 1.3130643286f;  // 1/sqrt(0.7^2+0.3^2)
#pragma unroll
    for (int i = 0; i < 4; i++) {
        int och = m0 + ty * 4 + i;
#pragma unroll
        for (int j = 0; j < 4; j++) {
            int s = n0 + tx * 4 + j;
            size_t idx = ((size_t)bb * CDIM + och) * HW + s;
            out[idx] = (0.7f * x[idx] + 0.3f * acc[i][j]) * norm;
        }
    }
}

extern "C" void kernel_launch(void* const* d_in, const int* in_sizes, int n_in,
                              void* d_out, int out_size) {
    const float* x     = (const float*)d_in[0];
    const float* ck    = (const float*)d_in[1];
    const float* cv    = (const float*)d_in[2];
    const float* wqkv  = (const float*)d_in[3];
    const float* wproj = (const float*)d_in[4];
    float* out = (float*)d_out;

    norm_kernel<<<4 * CDIM, 128>>>(wqkv, wproj);
    rope_table_kernel<<<8, 256>>>();
    qkv_gemm_kernel<<<dim3(4, 24, 4), 256>>>(x);

    int smem = 4 * 64 * SK * (int)sizeof(float);  // 73728 B -> 2 CTAs/SM
    cudaFuncSetAttribute(attn_kernel, cudaFuncAttributeMaxDynamicSharedMemorySize, smem);
    attn_kernel<<<dim3(8, NH, 4), 128, smem>>>(ck, cv);

    combine_kernel<<<dim3(2, NH, BATCH), 256>>>();
    proj_kernel<<<dim3(4, 8, 4), 256>>>(x, out);
}

// round 10
// speedup vs baseline: 1.8113x; 1.0492x over previous
#include <cuda_runtime.h>
#include <math.h>
#include <stdint.h>

#define NH 8
#define CDIM 512
#define HW 256
#define CH 64
#define BATCH 4
#define TCACHE 63
#define SK 72                 // smem row stride (words), attention
#define NKV 4
#define ITERS 64
#define LOG2E 1.4426950408889634f

__device__ float g_wqkv_n[3 * CDIM * CDIM];   // normalized, tf32, pc8-permuted on k
__device__ float g_wproj_n[CDIM * CDIM];      // normalized, plain fp32
__device__ float g_xt[BATCH * HW * CDIM];     // x^T: [b][s][k_phys], tf32
__device__ float2 g_rope[64 * 32];
__device__ float g_q[BATCH * NH * HW * CH];
__device__ float g_k[BATCH * NH * HW * CH];
__device__ float g_v[BATCH * NH * HW * CH];
__device__ float g_o[BATCH * CDIM * HW];
__device__ float g_po[BATCH * NH * 2 * NKV * 64 * 128];
__device__ float g_pl[BATCH * NH * 2 * NKV * 128];

__device__ __forceinline__ unsigned f2tf(float x) {
    unsigned r;
    asm("cvt.rna.tf32.f32 %0, %1;" : "=r"(r) : "f"(x));
    return r;
}
__device__ __forceinline__ float ex2(float x) {
    float y;
    asm("ex2.approx.f32 %0, %1;" : "=f"(y) : "f"(x));
    return y;
}
__device__ __forceinline__ void mma8(float c[4], const unsigned a[4], unsigned b0, unsigned b1) {
    asm volatile(
        "mma.sync.aligned.m16n8k8.row.col.f32.tf32.tf32.f32 "
        "{%0,%1,%2,%3}, {%4,%5,%6,%7}, {%8,%9}, {%0,%1,%2,%3};\n"
        : "+f"(c[0]), "+f"(c[1]), "+f"(c[2]), "+f"(c[3])
        : "r"(a[0]), "r"(a[1]), "r"(a[2]), "r"(a[3]), "r"(b0), "r"(b1));
}
__device__ __forceinline__ int pc8(int r) { return ((r & 3) << 1) | (r >> 2); }

__device__ __forceinline__ void cpa16(uint32_t dst, const void* src) {
    asm volatile("cp.async.cg.shared.global [%0], [%1], 16;" :: "r"(dst), "l"(src));
}
#define CP_COMMIT() asm volatile("cp.async.commit_group;")
#define CP_WAIT1()  asm volatile("cp.async.wait_group 1;")
#define CP_WAIT0()  asm volatile("cp.async.wait_group 0;")

// ---------------- K1a: mp_weight normalization (+ tf32/permute for wqkv) ----------------
__global__ void norm_kernel(const float* __restrict__ wq, const float* __restrict__ wp) {
    int r = blockIdx.x;
    bool is_q = (r < 3 * CDIM);
    const float* src = is_q ? wq + (size_t)r * CDIM : wp + (size_t)(r - 3 * CDIM) * CDIM;
    float* dst = is_q ? g_wqkv_n + (size_t)r * CDIM : g_wproj_n + (size_t)(r - 3 * CDIM) * CDIM;

    float4 v = reinterpret_cast<const float4*>(src)[threadIdx.x];
    float ss = v.x * v.x + v.y * v.y + v.z * v.z + v.w * v.w;
    for (int o = 16; o; o >>= 1) ss += __shfl_xor_sync(0xffffffffu, ss, o);
    __shared__ float wsum[4];
    if ((threadIdx.x & 31) == 0) wsum[threadIdx.x >> 5] = ss;
    __syncthreads();
    float nrm = sqrtf(wsum[0] + wsum[1] + wsum[2] + wsum[3]);
    float s512 = sqrtf((float)CDIM);
    float scale = 1.0f / ((1e-4f + nrm / s512) * s512);
    float o4[4] = {v.x * scale, v.y * scale, v.z * scale, v.w * scale};
    int c0 = threadIdx.x * 4;
    if (is_q) {
#pragma unroll
        for (int j = 0; j < 4; j++) {
            int c = c0 + j;
            dst[(c & ~7) | pc8(c & 7)] = __uint_as_float(f2tf(o4[j]));
        }
    } else {
        float4 w4 = make_float4(o4[0], o4[1], o4[2], o4[3]);
        reinterpret_cast<float4*>(dst)[threadIdx.x] = w4;
    }
}

// ---------------- K1b: rope table ----------------
__global__ void rope_table_kernel() {
    int idx = blockIdx.x * blockDim.x + threadIdx.x;
    if (idx < 64 * 32) {
        int t = idx >> 5, j = idx & 31;
        float inv = powf(10000.0f, -(2.0f * (float)j) / 64.0f);
        float a = (float)t * inv;
        g_rope[idx] = make_float2(cosf(a), sinf(a));
    }
}

// ---------------- K1c: x transpose -> g_xt[b][s][k_phys] (tf32) ----------------
__global__ void xt_kernel(const float* __restrict__ x) {
    __shared__ float t[32][33];
    int bb = blockIdx.z;
    int k0 = blockIdx.x * 32, s0 = blockIdx.y * 32;
    int tx = threadIdx.x, ty = threadIdx.y;
#pragma unroll
    for (int j = 0; j < 4; j++)
        t[ty + j * 8][tx] = x[((size_t)bb * CDIM + (k0 + ty + j * 8)) * HW + s0 + tx];
    __syncthreads();
    int kp = k0 + ((tx & ~7) | pc8(tx & 7));
#pragma unroll
    for (int j = 0; j < 4; j++)
        g_xt[((size_t)bb * HW + s0 + ty + j * 8) * CDIM + kp] =
            __uint_as_float(f2tf(t[tx][ty + j * 8]));
}

// ---------------- K2: QKV GEMM (tf32 mma) -> q/k/v [b][head][s][ch] ----------------
// grid (4 sblk, 24 oblk, 4 b), 128 thr. C[s64][outC64] = xt[s][k] . wqkv[outC][k]
#define QS 20   // smem row stride (words)
__global__ __launch_bounds__(128) void qkv_gemm_kernel() {
    __shared__ float As[2][64 * QS];
    __shared__ float Bs[2][64 * QS];
    int sblk = blockIdx.x, oblk = blockIdx.y, bb = blockIdx.z;
    int tid = threadIdx.x;
    int w = tid >> 5, l = tid & 31;
    int la = l >> 2, lb = l & 3;

    const float* xa = g_xt + ((size_t)bb * HW + sblk * 64) * CDIM;
    const float* wb = g_wqkv_n + (size_t)oblk * 64 * CDIM;

    int row = tid >> 1, half = tid & 1;
    uint32_t as_u[2] = {(uint32_t)__cvta_generic_to_shared(As[0]),
                        (uint32_t)__cvta_generic_to_shared(As[1])};
    uint32_t bs_u[2] = {(uint32_t)__cvta_generic_to_shared(Bs[0]),
                        (uint32_t)__cvta_generic_to_shared(Bs[1])};

    auto load_stage = [&](int kc) {
        int st = kc & 1;
        uint32_t ad = as_u[st] + (uint32_t)(row * QS + half * 8) * 4u;
        uint32_t bd = bs_u[st] + (uint32_t)(row * QS + half * 8) * 4u;
        const float* asrc = xa + (size_t)row * CDIM + kc * 16 + half * 8;
        const float* bsrc = wb + (size_t)row * CDIM + kc * 16 + half * 8;
        cpa16(ad, asrc); cpa16(ad + 16, asrc + 4);
        cpa16(bd, bsrc); cpa16(bd + 16, bsrc + 4);
    };

    float acc[8][4] = {};
    load_stage(0); CP_COMMIT();

    for (int kc = 0; kc < 32; kc++) {
        if (kc + 1 < 32) { load_stage(kc + 1); CP_COMMIT(); CP_WAIT1(); }
        else CP_WAIT0();
        __syncthreads();
        const float* Ab = As[kc & 1];
        const float* Bb = Bs[kc & 1];
#pragma unroll
        for (int c2 = 0; c2 < 2; c2++) {
            uint2 a0 = *reinterpret_cast<const uint2*>(&Ab[(w * 16 + la) * QS + c2 * 8 + 2 * lb]);
            uint2 a1 = *reinterpret_cast<const uint2*>(&Ab[(w * 16 + la + 8) * QS + c2 * 8 + 2 * lb]);
            unsigned A[4] = {a0.x, a1.x, a0.y, a1.y};
#pragma unroll
            for (int nn = 0; nn < 8; nn++) {
                uint2 b = *reinterpret_cast<const uint2*>(&Bb[(nn * 8 + la) * QS + c2 * 8 + 2 * lb]);
                mma8(acc[nn], A, b.x, b.y);
            }
        }
        __syncthreads();
    }

    int which = oblk >> 3;
    int head = oblk & 7;
    float* dst = ((which == 0) ? g_q : (which == 1) ? g_k : g_v) +
                 (size_t)(bb * NH + head) * HW * CH;
    int srow = sblk * 64 + w * 16 + la;
#pragma unroll
    for (int nn = 0; nn < 8; nn++) {
        int ch = nn * 8 + 2 * lb;
        *reinterpret_cast<float2*>(&dst[(size_t)srow * CH + ch]) =
            make_float2(acc[nn][0], acc[nn][1]);
        *reinterpret_cast<float2*>(&dst[(size_t)(srow + 8) * CH + ch]) =
            make_float2(acc[nn][2], acc[nn][3]);
    }
}

// ---------------- K3: flash attention v6 ----------------
// 128 thr, 2 q-tiles/warp, 4-way KV split, P-in-regs, fixed max, hoisted K frags.
__global__ __launch_bounds__(128, 2) void attn_kernel(const float* __restrict__ ck,
                                                      const float* __restrict__ cv) {
    extern __shared__ float smf[];
    float* Kr = smf;                  // 2 stages x 64 x SK | prologue: Q staging
    float* Vr = smf + 2 * 64 * SK;
    float* Vt = smf + 3 * 64 * SK;

    int qp = blockIdx.x >> 2, kvq = blockIdx.x & 3;
    int head = blockIdx.y, bb = blockIdx.z;
    int bhi = bb * NH + head;
    int tid = threadIdx.x;
    int w = tid >> 5, l = tid & 31;
    int la = l >> 2, lb = l & 3;

    uint32_t kr_u = (uint32_t)__cvta_generic_to_shared(Kr);
    uint32_t vr_u = (uint32_t)__cvta_generic_to_shared(Vr);

    auto src_ptr = [&](const float* cache, const float* cur, int i) -> const float* {
        int ktg = kvq * ITERS + i;
        int t = ktg >> 2, st = ktg & 3;
        if (t < TCACHE)
            return cache + ((((size_t)bhi * TCACHE + t) * HW + st * 64)) * CH;
        return cur + (((size_t)bhi * HW + st * 64)) * CH;
    };

    int krow = tid >> 1, half = tid & 1;
    int krow_p = (krow & ~7) | pc8(krow & 7);

    auto issue_k = [&](int i) {
        const float* kp = src_ptr(ck, g_k, i);
        int s = i & 1;
        uint32_t kd = kr_u + (uint32_t)(s * 64 * SK + krow_p * SK + half * 32) * 4u;
        const float* ks = kp + krow * CH + half * 32;
#pragma unroll
        for (int c = 0; c < 8; c++) cpa16(kd + c * 16, ks + c * 4);
    };
    auto issue_v = [&](int i) {
        const float* vp = src_ptr(cv, g_v, i);
        uint32_t vd = vr_u + (uint32_t)(krow * SK + half * 32) * 4u;
        const float* vs = vp + krow * CH + half * 32;
#pragma unroll
        for (int c = 0; c < 8; c++) cpa16(vd + c * 16, vs + c * 4);
    };

    // prologue: stage Q (rope pos 63, * log2e/8, tf32, permuted) into Kr region
    {
        int r = tid;
        const float* qpv = g_q + (((size_t)bhi) * HW + qp * 128 + r) * CH;
        const float2* tq = g_rope + 63 * 32;
        const float sc = 0.125f * LOG2E;
        unsigned* pr = reinterpret_cast<unsigned*>(Kr + r * SK);
#pragma unroll
        for (int g = 0; g < 8; g++) {
            float4 x0 = *reinterpret_cast<const float4*>(qpv + 8 * g);
            float4 x1 = *reinterpret_cast<const float4*>(qpv + 8 * g + 4);
            float2 t0 = tq[4 * g], t1 = tq[4 * g + 1], t2 = tq[4 * g + 2], t3 = tq[4 * g + 3];
            float l0 = (x0.x * t0.x - x0.y * t0.y) * sc;
            float l1 = (x0.x * t0.y + x0.y * t0.x) * sc;
            float l2 = (x0.z * t1.x - x0.w * t1.y) * sc;
            float l3 = (x0.z * t1.y + x0.w * t1.x) * sc;
            float l4 = (x1.x * t2.x - x1.y * t2.y) * sc;
            float l5 = (x1.x * t2.y + x1.y * t2.x) * sc;
            float l6 = (x1.z * t3.x - x1.w * t3.y) * sc;
            float l7 = (x1.z * t3.y + x1.w * t3.x) * sc;
            pr[8 * g + 0] = f2tf(l0); pr[8 * g + 1] = f2tf(l4);
            pr[8 * g + 2] = f2tf(l1); pr[8 * g + 3] = f2tf(l5);
            pr[8 * g + 4] = f2tf(l2); pr[8 * g + 5] = f2tf(l6);
            pr[8 * g + 6] = f2tf(l3); pr[8 * g + 7] = f2tf(l7);
        }
    }
    __syncthreads();

    unsigned qa[2][8][4];
#pragma unroll
    for (int tt = 0; tt < 2; tt++) {
        int r0 = tt * 64 + 16 * w + la;
#pragma unroll
        for (int kk = 0; kk < 8; kk++) {
            uint2 p0 = *reinterpret_cast<const uint2*>(&Kr[r0 * SK + kk * 8 + 2 * lb]);
            uint2 p1 = *reinterpret_cast<const uint2*>(&Kr[(r0 + 8) * SK + kk * 8 + 2 * lb]);
            qa[tt][kk][0] = p0.x; qa[tt][kk][1] = p1.x; qa[tt][kk][2] = p0.y; qa[tt][kk][3] = p1.y;
        }
    }
    __syncthreads();

    issue_k(0); issue_v(0); CP_COMMIT();
    issue_k(1); CP_COMMIT();

    float oacc[2][8][4] = {};
    float ls[2][2] = {};

    for (int i = 0; i < ITERS; i++) {
        int s = i & 1;
        CP_WAIT1();   // own cp.async data visible to self; no CTA barrier needed here

        // ---- convert own rows: K rope+permute in place; V transpose into Vt ----
        {
            int t = (kvq * ITERS + i) >> 2;
            float* kb = Kr + s * 64 * SK + krow_p * SK;
            const float2* tt_ = g_rope + t * 32 + half * 16;
#pragma unroll
            for (int g2 = 0; g2 < 4; g2++) {
                int ch0 = (half * 4 + g2) * 8;
                float4 a = *reinterpret_cast<const float4*>(kb + ch0);
                float4 b = *reinterpret_cast<const float4*>(kb + ch0 + 4);
                float2 t0 = tt_[4 * g2], t1 = tt_[4 * g2 + 1], t2 = tt_[4 * g2 + 2], t3 = tt_[4 * g2 + 3];
                float l0 = a.x * t0.x - a.y * t0.y;
                float l1 = a.x * t0.y + a.y * t0.x;
                float l2 = a.z * t1.x - a.w * t1.y;
                float l3 = a.z * t1.y + a.w * t1.x;
                float l4 = b.x * t2.x - b.y * t2.y;
                float l5 = b.x * t2.y + b.y * t2.x;
                float l6 = b.z * t3.x - b.w * t3.y;
                float l7 = b.z * t3.y + b.w * t3.x;
                unsigned* o = reinterpret_cast<unsigned*>(kb + ch0);
                o[0] = f2tf(l0); o[1] = f2tf(l4); o[2] = f2tf(l1); o[3] = f2tf(l5);
                o[4] = f2tf(l2); o[5] = f2tf(l6); o[6] = f2tf(l3); o[7] = f2tf(l7);
            }
            float* vb = Vr + krow * SK;
            unsigned* vt = reinterpret_cast<unsigned*>(Vt);
#pragma unroll
            for (int c = 0; c < 8; c++) {
                int ch0 = half * 32 + c * 4;
                float4 v = *reinterpret_cast<const float4*>(vb + ch0);
                vt[(ch0 + 0) * SK + krow_p] = f2tf(v.x);
                vt[(ch0 + 1) * SK + krow_p] = f2tf(v.y);
                vt[(ch0 + 2) * SK + krow_p] = f2tf(v.z);
                vt[(ch0 + 3) * SK + krow_p] = f2tf(v.w);
            }
        }
        __syncthreads();   // converted K/Vt visible CTA-wide

        if (i + 1 < ITERS) issue_v(i + 1);
        CP_COMMIT();

        // ---- S = QK^T with hoisted K frags; P = exp2 into pa ----
        const float* Kb = Kr + s * 64 * SK;
        unsigned pa[2][8][4];
        float s00 = 0.f, s01 = 0.f, s10 = 0.f, s11 = 0.f;
#pragma unroll
        for (int nn = 0; nn < 8; nn++) {
            const float* kr = Kb + (nn * 8 + la) * SK;
            uint2 bf[8];
#pragma unroll
            for (int kk = 0; kk < 8; kk++)
                bf[kk] = *reinterpret_cast<const uint2*>(kr + kk * 8 + 2 * lb);
#pragma unroll
            for (int tt = 0; tt < 2; tt++) {
                float c[4] = {0.f, 0.f, 0.f, 0.f};
#pragma unroll
                for (int kk = 0; kk < 8; kk++) mma8(c, qa[tt][kk], bf[kk].x, bf[kk].y);
                float p0 = ex2(c[0]);
                float p1 = ex2(c[1]);
                float p2 = ex2(c[2]);
                float p3 = ex2(c[3]);
                if (tt == 0) { s00 += p0 + p1; s01 += p2 + p3; }
                else         { s10 += p0 + p1; s11 += p2 + p3; }
                pa[tt][nn][0] = __float_as_uint(p0);
                pa[tt][nn][1] = __float_as_uint(p2);
                pa[tt][nn][2] = __float_as_uint(p1);
                pa[tt][nn][3] = __float_as_uint(p3);
            }
        }
        s00 += __shfl_xor_sync(0xffffffffu, s00, 1);
        s00 += __shfl_xor_sync(0xffffffffu, s00, 2);
        s01 += __shfl_xor_sync(0xffffffffu, s01, 1);
        s01 += __shfl_xor_sync(0xffffffffu, s01, 2);
        s10 += __shfl_xor_sync(0xffffffffu, s10, 1);
        s10 += __shfl_xor_sync(0xffffffffu, s10, 2);
        s11 += __shfl_xor_sync(0xffffffffu, s11, 1);
        s11 += __shfl_xor_sync(0xffffffffu, s11, 2);
        ls[0][0] += s00; ls[0][1] += s01;
        ls[1][0] += s10; ls[1][1] += s11;

        // ---- O += P V ----
#pragma unroll
        for (int kk = 0; kk < 8; kk++) {
#pragma unroll
            for (int nn = 0; nn < 8; nn++) {
                uint2 b = *reinterpret_cast<const uint2*>(&Vt[(nn * 8 + la) * SK + kk * 8 + 2 * lb]);
                mma8(oacc[0][nn], pa[0][kk], b.x, b.y);
                mma8(oacc[1][nn], pa[1][kk], b.x, b.y);
            }
        }

        __syncthreads();   // Kr(s)/Vt reads done before overwrite
        if (i + 2 < ITERS) issue_k(i + 2);
        CP_COMMIT();
    }

    // ---- epilogue ----
    int pbase = ((bhi * 2 + qp) * NKV + kvq);
    float* po = g_po + (size_t)pbase * 8192;
    int prow = 16 * w + la;
#pragma unroll
    for (int tt = 0; tt < 2; tt++) {
        int row = tt * 64 + prow;
#pragma unroll
        for (int nn = 0; nn < 8; nn++) {
            int ch = nn * 8 + 2 * lb;
            po[(ch + 0) * 128 + row]     = oacc[tt][nn][0];
            po[(ch + 1) * 128 + row]     = oacc[tt][nn][1];
            po[(ch + 0) * 128 + row + 8] = oacc[tt][nn][2];
            po[(ch + 1) * 128 + row + 8] = oacc[tt][nn][3];
        }
        if (lb == 0) {
            g_pl[pbase * 128 + row]     = ls[tt][0];
            g_pl[pbase * 128 + row + 8] = ls[tt][1];
        }
    }
}

// ---------------- K3b: split-KV combine ----------------
__global__ __launch_bounds__(256) void combine_kernel() {
    int qp = blockIdx.x, head = blockIdx.y, bb = blockIdx.z;
    int pb = (((bb * NH + head) * 2 + qp) * NKV);
    int tid = threadIdx.x;
    __shared__ float il[128];
    if (tid < 128) {
        float den = 0.f;
#pragma unroll
        for (int k = 0; k < NKV; k++) den += g_pl[(pb + k) * 128 + tid];
        il[tid] = 1.0f / den;
    }
    __syncthreads();
    int ch = tid >> 2, sg = tid & 3;
    float* dst = g_o + ((size_t)bb * CDIM + (ch * NH + head)) * HW + qp * 128;
#pragma unroll 4
    for (int rr = 0; rr < 32; rr++) {
        int r = sg * 32 + rr;
        float acc = 0.f;
#pragma unroll
        for (int k = 0; k < NKV; k++)
            acc += g_po[(size_t)(pb + k) * 8192 + ch * 128 + r];
        dst[r] = acc * il[r];
    }
}

// ---------------- K4: proj GEMM + mp_sum (fp32) ----------------
__global__ __launch_bounds__(256) void proj_kernel(const float* __restrict__ x,
                                                   float* __restrict__ out) {
    __shared__ float As[16][68];
    __shared__ float Bs[16][68];
    int bb = blockIdx.z;
    int m0 = blockIdx.y * 64;
    int n0 = blockIdx.x * 64;
    int tid = threadIdx.x;
    int ty = tid >> 4, tx = tid & 15;
    float acc[4][4] = {};

    for (int k0 = 0; k0 < CDIM; k0 += 16) {
        {
            int lin = tid * 4;
            int mi = lin >> 4, ki = lin & 15;
            float4 a = *reinterpret_cast<const float4*>(&g_wproj_n[(size_t)(m0 + mi) * CDIM + k0 + ki]);
            As[ki + 0][mi] = a.x; As[ki + 1][mi] = a.y; As[ki + 2][mi] = a.z; As[ki + 3][mi] = a.w;
        }
        {
            int lin = tid * 4;
            int ki = lin >> 6, ni = lin & 63;
            float4 b = *reinterpret_cast<const float4*>(&g_o[((size_t)bb * CDIM + k0 + ki) * HW + n0 + ni]);
            *reinterpret_cast<float4*>(&Bs[ki][ni]) = b;
        }
        __syncthreads();
#pragma unroll
        for (int kk = 0; kk < 16; kk++) {
            float4 a = *reinterpret_cast<const float4*>(&As[kk][ty * 4]);
            float4 b = *reinterpret_cast<const float4*>(&Bs[kk][tx * 4]);
            float av[4] = {a.x, a.y, a.z, a.w};
            float bv[4] = {b.x, b.y, b.z, b.w};
#pragma unroll
            for (int i = 0; i < 4; i++)
#pragma unroll
                for (int j = 0; j < 4; j++) acc[i][j] += av[i] * bv[j];
        }
        __syncthreads();
    }

    const float norm = 1.3130643286f;
#pragma unroll
    for (int i = 0; i < 4; i++) {
        int och = m0 + ty * 4 + i;
#pragma unroll
        for (int j = 0; j < 4; j++) {
            int s = n0 + tx * 4 + j;
            size_t idx = ((size_t)bb * CDIM + och) * HW + s;
            out[idx] = (0.7f * x[idx] + 0.3f * acc[i][j]) * norm;
        }
    }
}

extern "C" void kernel_launch(void* const* d_in, const int* in_sizes, int n_in,
                              void* d_out, int out_size) {
    const float* x     = (const float*)d_in[0];
    const float* ck    = (const float*)d_in[1];
    const float* cv    = (const float*)d_in[2];
    const float* wqkv  = (const float*)d_in[3];
    const float* wproj = (const float*)d_in[4];
    float* out = (float*)d_out;

    norm_kernel<<<4 * CDIM, 128>>>(wqkv, wproj);
    rope_table_kernel<<<8, 256>>>();
    xt_kernel<<<dim3(16, 8, 4), dim3(32, 8)>>>(x);
    qkv_gemm_kernel<<<dim3(4, 24, 4), 128>>>();

    int smem = 4 * 64 * SK * (int)sizeof(float);  // 73728 B -> 2 CTAs/SM
    cudaFuncSetAttribute(attn_kernel, cudaFuncAttributeMaxDynamicSharedMemorySize, smem);
    attn_kernel<<<dim3(8, NH, 4), 128, smem>>>(ck, cv);

    combine_kernel<<<dim3(2, NH, BATCH), 256>>>();
    proj_kernel<<<dim3(4, 8, 4), 256>>>(x, out);
}